// round 12
// baseline (speedup 1.0000x reference)
#include <cuda_runtime.h>

// ---------------- static problem sizes ----------------
#define N_NODES 20000
#define E_EDGES 320000
#define B_Q 4
#define K_T 32
#define D_DIM 32
#define DR_REL 40
#define T_STEPS 10
#define VTH 2.0f
#define DECAY 0.7788007830714049f   // exp(-1/4)
#define RATIO 0.95f
#define NSCALE 8.025261215232422f   // (1 - 0.95^10) / (1 - 0.95)

#define NTHR 128
#define NW 4                         // warps per block

// ---------------- persistent state (zero-init; cleanup restores zeros) ----------------
// Fast path touches NONE of these.
__device__ unsigned g_smask[T_STEPS * N_NODES * B_Q];
__device__ float    g_v[N_NODES * B_Q * D_DIM];
__device__ float    g_c[N_NODES * B_Q * D_DIM];
__device__ float    g_agg[N_NODES * B_Q * D_DIM];
__device__ int      g_hot_flag[N_NODES];
__device__ int      g_hot_list[N_NODES];
__device__ float    g_wrel[B_Q * DR_REL * D_DIM];

__global__ __launch_bounds__(NTHR, 1)
void fused_kernel(const int* __restrict__ edge_src,
                  const int* __restrict__ edge_dst,
                  const int* __restrict__ edge_type,
                  const int* __restrict__ h_index,
                  const int* __restrict__ t_index,
                  const int* __restrict__ r_index,
                  const float* __restrict__ query_emb,
                  const float* __restrict__ relw_W,
                  const float* __restrict__ relw_b,
                  const float* __restrict__ lin_W,
                  const float* __restrict__ lin_b,
                  const float* __restrict__ W1,
                  const float* __restrict__ b1,
                  const float* __restrict__ W2,
                  const float* __restrict__ b2,
                  float* __restrict__ out) {
    __shared__ float    s_qe[DR_REL * D_DIM];   // full query_emb table (5 KB)
    __shared__ unsigned s_any[NW];              // per-warp t=0 ballots (own slot)
    __shared__ int      s_r[NW];
    // slow-path shared (untouched on fast path)
    __shared__ float s_W1[64 * 65];
    __shared__ float s_WT[D_DIM * D_DIM];
    __shared__ float s_q[B_Q * D_DIM];
    __shared__ float s_b1[64], s_W2[64];
    __shared__ int   s_hot, s_fprev, s_fcur, s_wrel_done;

    const int tid  = threadIdx.x;
    const int lane = tid & 31;
    const int warp = tid >> 5;               // == batch b on the fast path

    // ---------- one parallel load round (no dependent global chains) ----------
    {   // query_emb: 320 float4, 128 threads -> 3 strided rounds, all independent
        const float4* qe4 = reinterpret_cast<const float4*>(query_emb);
        float4* sqe4 = reinterpret_cast<float4*>(s_qe);
#pragma unroll
        for (int i = tid; i < (DR_REL * D_DIM) / 4; i += NTHR)
            sqe4[i] = __ldg(qe4 + i);
    }
    if (lane == 0) s_r[warp] = __ldg(r_index + warp);
    const float4* W14 = reinterpret_cast<const float4*>(W1);
    float4 wa[8], wb[8];                     // W1[lane][32:64], W1[lane+32][32:64]
#pragma unroll
    for (int qd = 0; qd < 8; ++qd) {
        wa[qd] = __ldg(W14 + lane * 16 + 8 + qd);
        wb[qd] = __ldg(W14 + (lane + 32) * 16 + 8 + qd);
    }
    float b1a = __ldg(b1 + lane), b1b = __ldg(b1 + lane + 32);
    float w2a = __ldg(W2 + lane), w2b = __ldg(W2 + lane + 32);
    float bb2 = __ldg(b2);
    if (tid == 0) { s_hot = 0; s_fprev = 0; s_fcur = 0; s_wrel_done = 0; }
    __syncthreads();                         // staged table ready

    const float qv = s_qe[s_r[warp] * D_DIM + lane];

    // ---------- t=0 spike ballot (strict decay => spikes only possible at t=0) ----------
    float boundary = qv * (VTH * 0.5f) + VTH * 0.5f;
    unsigned m0 = __ballot_sync(0xffffffffu, (boundary - VTH) >= 0.f);
    if (lane == 0) s_any[warp] = m0;

    // ---------- speculative MLP on feat = [0, q_b] (valid iff no spikes anywhere) ----------
    float acc0 = b1a, acc1 = b1b;
#pragma unroll
    for (int qd = 0; qd < 8; ++qd) {
        float c0 = __shfl_sync(0xffffffffu, qv, qd * 4 + 0);
        float c1 = __shfl_sync(0xffffffffu, qv, qd * 4 + 1);
        float c2 = __shfl_sync(0xffffffffu, qv, qd * 4 + 2);
        float c3 = __shfl_sync(0xffffffffu, qv, qd * 4 + 3);
        acc0 = fmaf(c0, wa[qd].x, acc0); acc1 = fmaf(c0, wb[qd].x, acc1);
        acc0 = fmaf(c1, wa[qd].y, acc0); acc1 = fmaf(c1, wb[qd].y, acc1);
        acc0 = fmaf(c2, wa[qd].z, acc0); acc1 = fmaf(c2, wb[qd].z, acc1);
        acc0 = fmaf(c3, wa[qd].w, acc0); acc1 = fmaf(c3, wb[qd].w, acc1);
    }
    float h = fmaxf(acc0, 0.f) * w2a + fmaxf(acc1, 0.f) * w2b;
#pragma unroll
    for (int off = 16; off; off >>= 1)
        h += __shfl_down_sync(0xffffffffu, h, off);
    h = __shfl_sync(0xffffffffu, h, 0) + bb2;

    __syncthreads();                         // ballots visible
    unsigned any = s_any[0] | s_any[1] | s_any[2] | s_any[3];

    // ======================= FAST PATH: no spikes ever =======================
    if (any == 0u) {
        out[warp * K_T + lane] = h;          // score depends only on b
        return;
    }

    // ======================= SLOW PATH (spikes at t=0 exist) =======================
    // stage q + full W1 + b1/W2 + lin_W^T into shared
    s_q[warp * D_DIM + lane] = qv;
    if (tid < 64) { s_b1[tid] = __ldg(b1 + tid); s_W2[tid] = __ldg(W2 + tid); }
    for (int k = tid; k < 1024; k += NTHR) {             // 1024 float4 of W1
        float4 v = __ldg(W14 + k);
        float* dst = s_W1 + (k >> 4) * 65 + ((k & 15) << 2);
        dst[0] = v.x; dst[1] = v.y; dst[2] = v.z; dst[3] = v.w;
    }
    for (int i = tid; i < D_DIM * D_DIM; i += NTHR) {
        int ii = i >> 5, j = i & 31;
        s_WT[i] = lin_W[j * D_DIM + ii];
    }
    // materialize head-node state at ts = 0
    {
        int b = warp;
        int n = __ldg(h_index + b);
        bool sp = (boundary - VTH) >= 0.f;
        size_t base = (size_t)(n * B_Q + b) * D_DIM + lane;
        g_v[base] = sp ? 0.f : boundary;
        g_c[base] = 0.f;
        if (lane == 0) {
            if (m0) {
                g_smask[(size_t)(n * B_Q) + b] = m0;     // t = 0 slice
                atomicAdd(&s_fprev, 1);
            }
            if (atomicExch(&g_hot_flag[n], 1) == 0) {
                int p = atomicAdd(&s_hot, 1);
                g_hot_list[p] = n;
            }
        }
    }
    __syncthreads();

    const float lb = __ldg(lin_b + lane);
    for (int t = 1; t < T_STEPS; ++t) {
        int fc = s_fprev;
        if (fc != 0) {
            if (!s_wrel_done) {
                for (int id = tid; id < B_Q * DR_REL * D_DIM; id += NTHR) {
                    int b  = id / (DR_REL * D_DIM);
                    int rd = id % (DR_REL * D_DIM);
                    float acc = relw_b[rd];
#pragma unroll
                    for (int i = 0; i < D_DIM; ++i)
                        acc += s_q[b * D_DIM + i] * relw_W[i * (DR_REL * D_DIM) + rd];
                    g_wrel[id] = acc;
                }
                __syncthreads();
                if (tid == 0) s_wrel_done = 1;
            }
            const unsigned* mp = g_smask + (size_t)(t - 1) * (N_NODES * B_Q);
            for (int e = warp; e < E_EDGES; e += NW) {
                int src = __ldg(edge_src + e);
                uint4 m = *reinterpret_cast<const uint4*>(mp + src * 4);
                if (m.x | m.y | m.z | m.w) {
                    int dst = __ldg(edge_dst + e);
                    int ty  = __ldg(edge_type + e);
                    if (lane == 0) {
                        if (atomicExch(&g_hot_flag[dst], 1) == 0) {
                            int p = atomicAdd(&s_hot, 1);
                            g_hot_list[p] = dst;
                        }
                    }
                    int off = ty * D_DIM + lane;
                    float* ag = g_agg + (size_t)(dst * B_Q) * D_DIM + lane;
                    if ((m.x >> lane) & 1u) atomicAdd(ag + 0 * D_DIM, g_wrel[0 * DR_REL * D_DIM + off]);
                    if ((m.y >> lane) & 1u) atomicAdd(ag + 1 * D_DIM, g_wrel[1 * DR_REL * D_DIM + off]);
                    if ((m.z >> lane) & 1u) atomicAdd(ag + 2 * D_DIM, g_wrel[2 * DR_REL * D_DIM + off]);
                    if ((m.w >> lane) & 1u) atomicAdd(ag + 3 * D_DIM, g_wrel[3 * DR_REL * D_DIM + off]);
                }
            }
            __syncthreads();
        }
        int nh = s_hot;
        for (int i = warp; i < nh; i += NW) {
            int n = g_hot_list[i];
            size_t base = (size_t)(n * B_Q) * D_DIM + lane;
            float a0 = 0.f, a1 = 0.f, a2 = 0.f, a3 = 0.f;
            if (fc != 0) {
                a0 = g_agg[base + 0 * D_DIM]; g_agg[base + 0 * D_DIM] = 0.f;
                a1 = g_agg[base + 1 * D_DIM]; g_agg[base + 1 * D_DIM] = 0.f;
                a2 = g_agg[base + 2 * D_DIM]; g_agg[base + 2 * D_DIM] = 0.f;
                a3 = g_agg[base + 3 * D_DIM]; g_agg[base + 3 * D_DIM] = 0.f;
            }
            float x0 = lb, x1 = lb, x2 = lb, x3 = lb;
#pragma unroll
            for (int k = 0; k < D_DIM; ++k) {
                float w = s_WT[k * D_DIM + lane];
                x0 = fmaf(__shfl_sync(0xffffffffu, a0, k), w, x0);
                x1 = fmaf(__shfl_sync(0xffffffffu, a1, k), w, x1);
                x2 = fmaf(__shfl_sync(0xffffffffu, a2, k), w, x2);
                x3 = fmaf(__shfl_sync(0xffffffffu, a3, k), w, x3);
            }
            unsigned bm[4];
            float xs[4] = {x0, x1, x2, x3};
#pragma unroll
            for (int b = 0; b < B_Q; ++b) {
                float c = g_c[base + b * D_DIM] * DECAY + xs[b];
                float v = g_v[base + b * D_DIM] * DECAY + c;
                bool sp = (v - VTH) >= 0.f;
                g_c[base + b * D_DIM] = c;
                g_v[base + b * D_DIM] = sp ? 0.f : v;
                bm[b] = __ballot_sync(0xffffffffu, sp);
            }
            if (lane == 0) {
                *reinterpret_cast<uint4*>(g_smask + (size_t)t * (N_NODES * B_Q) + n * B_Q) =
                    make_uint4(bm[0], bm[1], bm[2], bm[3]);
                if (bm[0] | bm[1] | bm[2] | bm[3]) atomicAdd(&s_fcur, 1);
            }
        }
        __syncthreads();
        if (tid == 0) { s_fprev = s_fcur; s_fcur = 0; }
        __syncthreads();
    }

    // full score: warp per (b,k), 32 rounds over 128 pairs
    for (int p = warp; p < B_Q * K_T; p += NW) {
        int b = p >> 5;                      // K_T == 32
        int tn = __ldg(t_index + p);
        float e = 0.f, w = 1.0f;
#pragma unroll
        for (int t = 0; t < T_STEPS; ++t) {
            unsigned m = g_smask[(size_t)t * (N_NODES * B_Q) + tn * B_Q + b];
            if ((m >> lane) & 1u) e += w;
            w *= RATIO;
        }
        float f0 = e / NSCALE;
        float f1 = s_q[b * D_DIM + lane];
        float acc0s = s_b1[lane], acc1s = s_b1[lane + 32];
#pragma unroll
        for (int i = 0; i < 32; ++i) {
            float a = __shfl_sync(0xffffffffu, f0, i);
            float c = __shfl_sync(0xffffffffu, f1, i);
            acc0s = fmaf(a, s_W1[lane * 65 + i],              acc0s);
            acc0s = fmaf(c, s_W1[lane * 65 + 32 + i],         acc0s);
            acc1s = fmaf(a, s_W1[(lane + 32) * 65 + i],       acc1s);
            acc1s = fmaf(c, s_W1[(lane + 32) * 65 + 32 + i],  acc1s);
        }
        float hs = fmaxf(acc0s, 0.f) * s_W2[lane] + fmaxf(acc1s, 0.f) * s_W2[lane + 32];
#pragma unroll
        for (int off = 16; off; off >>= 1)
            hs += __shfl_down_sync(0xffffffffu, hs, off);
        if (lane == 0) out[p] = hs + bb2;
    }
    __syncthreads();

    // cleanup: restore pristine zeros for next replay
    {
        int nh = s_hot;
        for (int i = warp; i < nh; i += NW) {
            int n = g_hot_list[i];
            size_t base = (size_t)(n * B_Q) * D_DIM + lane;
#pragma unroll
            for (int b = 0; b < B_Q; ++b) {
                g_v[base + b * D_DIM]   = 0.f;
                g_c[base + b * D_DIM]   = 0.f;
                g_agg[base + b * D_DIM] = 0.f;
            }
            if (lane < T_STEPS)
                *reinterpret_cast<uint4*>(g_smask + (size_t)lane * (N_NODES * B_Q) + n * B_Q) =
                    make_uint4(0u, 0u, 0u, 0u);
            if (lane == 0) g_hot_flag[n] = 0;
        }
    }
}

// ---------------- launch ----------------
extern "C" void kernel_launch(void* const* d_in, const int* in_sizes, int n_in,
                              void* d_out, int out_size) {
    fused_kernel<<<1, NTHR>>>(
        (const int*)d_in[0], (const int*)d_in[1], (const int*)d_in[2],
        (const int*)d_in[3], (const int*)d_in[4], (const int*)d_in[5],
        (const float*)d_in[6], (const float*)d_in[7], (const float*)d_in[8],
        (const float*)d_in[9], (const float*)d_in[10],
        (const float*)d_in[11], (const float*)d_in[12],
        (const float*)d_in[13], (const float*)d_in[14],
        (float*)d_out);
}

// round 13
// speedup vs baseline: 1.0152x; 1.0152x over previous
#include <cuda_runtime.h>

// ---------------- static problem sizes ----------------
#define N_NODES 20000
#define E_EDGES 320000
#define B_Q 4
#define K_T 32
#define D_DIM 32
#define DR_REL 40
#define T_STEPS 10
#define VTH 2.0f
#define DECAY 0.7788007830714049f   // exp(-1/4)
#define RATIO 0.95f
#define NSCALE 8.025261215232422f   // (1 - 0.95^10) / (1 - 0.95)

// ---------------- persistent state (zero-init; cleanup restores zeros) ----------------
// Fast path touches NONE of these.
__device__ unsigned g_smask[T_STEPS * N_NODES * B_Q];
__device__ float    g_v[N_NODES * B_Q * D_DIM];
__device__ float    g_c[N_NODES * B_Q * D_DIM];
__device__ float    g_agg[N_NODES * B_Q * D_DIM];
__device__ int      g_hot_flag[N_NODES];
__device__ int      g_hot_list[N_NODES];
__device__ float    g_wrel[B_Q * DR_REL * D_DIM];

__global__ __launch_bounds__(32, 1)
void fused_kernel(const int* __restrict__ edge_src,
                  const int* __restrict__ edge_dst,
                  const int* __restrict__ edge_type,
                  const int* __restrict__ h_index,
                  const int* __restrict__ t_index,
                  const int* __restrict__ r_index,
                  const float* __restrict__ query_emb,
                  const float* __restrict__ relw_W,
                  const float* __restrict__ relw_b,
                  const float* __restrict__ lin_W,
                  const float* __restrict__ lin_b,
                  const float* __restrict__ W1,
                  const float* __restrict__ b1,
                  const float* __restrict__ W2,
                  const float* __restrict__ b2,
                  float* __restrict__ out) {
    // slow-path shared (untouched on fast path)
    __shared__ float s_W1[64 * 65];
    __shared__ float s_WT[D_DIM * D_DIM];
    __shared__ float s_q[B_Q * D_DIM];
    __shared__ float s_b1[64], s_W2[64];
    __shared__ int   s_hot, s_fprev, s_fcur, s_wrel_done;

    const int lane = threadIdx.x;            // single warp

    // ---------- all fast-path loads, maximum overlap ----------
    int r = 0;
    if (lane < B_Q) r = __ldg(r_index + lane);           // one 16B transaction
    const float4* W14 = reinterpret_cast<const float4*>(W1);
    float4 wa[8], wb[8];                     // W1[lane][32:64], W1[lane+32][32:64]
#pragma unroll
    for (int qd = 0; qd < 8; ++qd) {
        wa[qd] = __ldg(W14 + lane * 16 + 8 + qd);
        wb[qd] = __ldg(W14 + (lane + 32) * 16 + 8 + qd);
    }
    float b1a = __ldg(b1 + lane), b1b = __ldg(b1 + lane + 32);
    float w2a = __ldg(W2 + lane), w2b = __ldg(W2 + lane + 32);
    float bb2 = __ldg(b2);
    int r0 = __shfl_sync(0xffffffffu, r, 0);
    int r1 = __shfl_sync(0xffffffffu, r, 1);
    int r2 = __shfl_sync(0xffffffffu, r, 2);
    int r3 = __shfl_sync(0xffffffffu, r, 3);
    float q0 = __ldg(query_emb + r0 * D_DIM + lane);     // 4 independent gathers
    float q1 = __ldg(query_emb + r1 * D_DIM + lane);
    float q2 = __ldg(query_emb + r2 * D_DIM + lane);
    float q3 = __ldg(query_emb + r3 * D_DIM + lane);

    // ---------- t=0 ballots (strict decay => spikes only possible at t=0) ----------
    float bd0 = q0 * (VTH * 0.5f) + VTH * 0.5f;
    float bd1 = q1 * (VTH * 0.5f) + VTH * 0.5f;
    float bd2 = q2 * (VTH * 0.5f) + VTH * 0.5f;
    float bd3 = q3 * (VTH * 0.5f) + VTH * 0.5f;
    unsigned m0 = __ballot_sync(0xffffffffu, (bd0 - VTH) >= 0.f);
    unsigned m1 = __ballot_sync(0xffffffffu, (bd1 - VTH) >= 0.f);
    unsigned m2 = __ballot_sync(0xffffffffu, (bd2 - VTH) >= 0.f);
    unsigned m3 = __ballot_sync(0xffffffffu, (bd3 - VTH) >= 0.f);
    const unsigned any = m0 | m1 | m2 | m3;  // register; no shared, no barrier

    // ======================= FAST PATH: no spikes ever =======================
    if (any == 0u) {
        // 4 MLPs interleaved; W1 register rows reused across batches
        const float* waf = reinterpret_cast<const float*>(wa);
        const float* wbf = reinterpret_cast<const float*>(wb);
        float a00 = b1a, a01 = b1b;          // batch 0: rows lane, lane+32
        float a10 = b1a, a11 = b1b;
        float a20 = b1a, a21 = b1b;
        float a30 = b1a, a31 = b1b;
#pragma unroll
        for (int i = 0; i < 32; ++i) {
            float wA = waf[i], wB = wbf[i];
            float c0 = __shfl_sync(0xffffffffu, q0, i);
            float c1 = __shfl_sync(0xffffffffu, q1, i);
            float c2 = __shfl_sync(0xffffffffu, q2, i);
            float c3 = __shfl_sync(0xffffffffu, q3, i);
            a00 = fmaf(c0, wA, a00); a01 = fmaf(c0, wB, a01);
            a10 = fmaf(c1, wA, a10); a11 = fmaf(c1, wB, a11);
            a20 = fmaf(c2, wA, a20); a21 = fmaf(c2, wB, a21);
            a30 = fmaf(c3, wA, a30); a31 = fmaf(c3, wB, a31);
        }
        float h0 = fmaxf(a00, 0.f) * w2a + fmaxf(a01, 0.f) * w2b;
        float h1 = fmaxf(a10, 0.f) * w2a + fmaxf(a11, 0.f) * w2b;
        float h2 = fmaxf(a20, 0.f) * w2a + fmaxf(a21, 0.f) * w2b;
        float h3 = fmaxf(a30, 0.f) * w2a + fmaxf(a31, 0.f) * w2b;
#pragma unroll
        for (int off = 16; off; off >>= 1) {
            h0 += __shfl_down_sync(0xffffffffu, h0, off);
            h1 += __shfl_down_sync(0xffffffffu, h1, off);
            h2 += __shfl_down_sync(0xffffffffu, h2, off);
            h3 += __shfl_down_sync(0xffffffffu, h3, off);
        }
        h0 = __shfl_sync(0xffffffffu, h0, 0) + bb2;
        h1 = __shfl_sync(0xffffffffu, h1, 0) + bb2;
        h2 = __shfl_sync(0xffffffffu, h2, 0) + bb2;
        h3 = __shfl_sync(0xffffffffu, h3, 0) + bb2;
        // out[b*32+k] = h_b : lane writes 4 floats (all same b = lane>>3)
        float sc = (lane < 16) ? ((lane < 8) ? h0 : h1) : ((lane < 24) ? h2 : h3);
        reinterpret_cast<float4*>(out)[lane] = make_float4(sc, sc, sc, sc);
        return;
    }

    // ======================= SLOW PATH (spikes at t=0 exist; single-warp generic) =======================
    s_q[0 * D_DIM + lane] = q0;
    s_q[1 * D_DIM + lane] = q1;
    s_q[2 * D_DIM + lane] = q2;
    s_q[3 * D_DIM + lane] = q3;
    for (int i = lane; i < 64; i += 32) { s_b1[i] = __ldg(b1 + i); s_W2[i] = __ldg(W2 + i); }
    for (int k = lane; k < 1024; k += 32) {              // full W1 into padded shared
        float4 v = __ldg(W14 + k);
        float* dst = s_W1 + (k >> 4) * 65 + ((k & 15) << 2);
        dst[0] = v.x; dst[1] = v.y; dst[2] = v.z; dst[3] = v.w;
    }
    for (int i = lane; i < D_DIM * D_DIM; i += 32) {
        int ii = i >> 5, j = i & 31;
        s_WT[i] = lin_W[j * D_DIM + ii];
    }
    if (lane == 0) { s_hot = 0; s_fprev = 0; s_fcur = 0; s_wrel_done = 0; }
    __syncthreads();

    // materialize head-node state at ts = 0
    {
        unsigned ms[4] = {m0, m1, m2, m3};
        for (int b = 0; b < B_Q; ++b) {
            int n = __ldg(h_index + b);
            float bd = s_q[b * D_DIM + lane] * (VTH * 0.5f) + VTH * 0.5f;
            bool sp = (bd - VTH) >= 0.f;
            size_t base = (size_t)(n * B_Q + b) * D_DIM + lane;
            g_v[base] = sp ? 0.f : bd;
            g_c[base] = 0.f;
            if (lane == 0) {
                if (ms[b]) {
                    g_smask[(size_t)(n * B_Q) + b] = ms[b];
                    s_fprev += 1;
                }
                if (atomicExch(&g_hot_flag[n], 1) == 0) {
                    int p = s_hot++;
                    g_hot_list[p] = n;
                }
            }
        }
    }
    __syncthreads();

    const float lb = __ldg(lin_b + lane);
    for (int t = 1; t < T_STEPS; ++t) {
        int fc = s_fprev;
        if (fc != 0) {
            if (!s_wrel_done) {
                for (int id = lane; id < B_Q * DR_REL * D_DIM; id += 32) {
                    int b  = id / (DR_REL * D_DIM);
                    int rd = id % (DR_REL * D_DIM);
                    float acc = relw_b[rd];
#pragma unroll
                    for (int i = 0; i < D_DIM; ++i)
                        acc += s_q[b * D_DIM + i] * relw_W[i * (DR_REL * D_DIM) + rd];
                    g_wrel[id] = acc;
                }
                __syncthreads();
                if (lane == 0) s_wrel_done = 1;
            }
            const unsigned* mp = g_smask + (size_t)(t - 1) * (N_NODES * B_Q);
            for (int e = 0; e < E_EDGES; ++e) {
                int src = __ldg(edge_src + e);
                uint4 m = *reinterpret_cast<const uint4*>(mp + src * 4);
                if (m.x | m.y | m.z | m.w) {
                    int dst = __ldg(edge_dst + e);
                    int ty  = __ldg(edge_type + e);
                    if (lane == 0) {
                        if (atomicExch(&g_hot_flag[dst], 1) == 0) {
                            int p = s_hot++;
                            g_hot_list[p] = dst;
                        }
                    }
                    int off = ty * D_DIM + lane;
                    float* ag = g_agg + (size_t)(dst * B_Q) * D_DIM + lane;
                    if ((m.x >> lane) & 1u) ag[0 * D_DIM] += g_wrel[0 * DR_REL * D_DIM + off];
                    if ((m.y >> lane) & 1u) ag[1 * D_DIM] += g_wrel[1 * DR_REL * D_DIM + off];
                    if ((m.z >> lane) & 1u) ag[2 * D_DIM] += g_wrel[2 * DR_REL * D_DIM + off];
                    if ((m.w >> lane) & 1u) ag[3 * D_DIM] += g_wrel[3 * DR_REL * D_DIM + off];
                }
            }
            __syncthreads();
        }
        int nh = s_hot;
        for (int i = 0; i < nh; ++i) {
            int n = g_hot_list[i];
            size_t base = (size_t)(n * B_Q) * D_DIM + lane;
            float a0 = 0.f, a1 = 0.f, a2 = 0.f, a3 = 0.f;
            if (fc != 0) {
                a0 = g_agg[base + 0 * D_DIM]; g_agg[base + 0 * D_DIM] = 0.f;
                a1 = g_agg[base + 1 * D_DIM]; g_agg[base + 1 * D_DIM] = 0.f;
                a2 = g_agg[base + 2 * D_DIM]; g_agg[base + 2 * D_DIM] = 0.f;
                a3 = g_agg[base + 3 * D_DIM]; g_agg[base + 3 * D_DIM] = 0.f;
            }
            float x0 = lb, x1 = lb, x2 = lb, x3 = lb;
#pragma unroll
            for (int k = 0; k < D_DIM; ++k) {
                float w = s_WT[k * D_DIM + lane];
                x0 = fmaf(__shfl_sync(0xffffffffu, a0, k), w, x0);
                x1 = fmaf(__shfl_sync(0xffffffffu, a1, k), w, x1);
                x2 = fmaf(__shfl_sync(0xffffffffu, a2, k), w, x2);
                x3 = fmaf(__shfl_sync(0xffffffffu, a3, k), w, x3);
            }
            unsigned bm[4];
            float xs[4] = {x0, x1, x2, x3};
#pragma unroll
            for (int b = 0; b < B_Q; ++b) {
                float c = g_c[base + b * D_DIM] * DECAY + xs[b];
                float v = g_v[base + b * D_DIM] * DECAY + c;
                bool sp = (v - VTH) >= 0.f;
                g_c[base + b * D_DIM] = c;
                g_v[base + b * D_DIM] = sp ? 0.f : v;
                bm[b] = __ballot_sync(0xffffffffu, sp);
            }
            if (lane == 0) {
                *reinterpret_cast<uint4*>(g_smask + (size_t)t * (N_NODES * B_Q) + n * B_Q) =
                    make_uint4(bm[0], bm[1], bm[2], bm[3]);
                if (bm[0] | bm[1] | bm[2] | bm[3]) s_fcur += 1;
            }
        }
        __syncthreads();
        if (lane == 0) { s_fprev = s_fcur; s_fcur = 0; }
        __syncthreads();
    }

    // full score: 128 pairs, serial over the single warp
    for (int p = 0; p < B_Q * K_T; ++p) {
        int b = p >> 5;                      // K_T == 32
        int tn = __ldg(t_index + p);
        float e = 0.f, w = 1.0f;
#pragma unroll
        for (int t = 0; t < T_STEPS; ++t) {
            unsigned m = g_smask[(size_t)t * (N_NODES * B_Q) + tn * B_Q + b];
            if ((m >> lane) & 1u) e += w;
            w *= RATIO;
        }
        float f0 = e / NSCALE;
        float f1 = s_q[b * D_DIM + lane];
        float acc0s = s_b1[lane], acc1s = s_b1[lane + 32];
#pragma unroll
        for (int i = 0; i < 32; ++i) {
            float a = __shfl_sync(0xffffffffu, f0, i);
            float c = __shfl_sync(0xffffffffu, f1, i);
            acc0s = fmaf(a, s_W1[lane * 65 + i],              acc0s);
            acc0s = fmaf(c, s_W1[lane * 65 + 32 + i],         acc0s);
            acc1s = fmaf(a, s_W1[(lane + 32) * 65 + i],       acc1s);
            acc1s = fmaf(c, s_W1[(lane + 32) * 65 + 32 + i],  acc1s);
        }
        float hs = fmaxf(acc0s, 0.f) * s_W2[lane] + fmaxf(acc1s, 0.f) * s_W2[lane + 32];
#pragma unroll
        for (int off = 16; off; off >>= 1)
            hs += __shfl_down_sync(0xffffffffu, hs, off);
        if (lane == 0) out[p] = hs + bb2;
    }
    __syncthreads();

    // cleanup: restore pristine zeros for next replay
    {
        int nh = s_hot;
        for (int i = 0; i < nh; ++i) {
            int n = g_hot_list[i];
            size_t base = (size_t)(n * B_Q) * D_DIM + lane;
#pragma unroll
            for (int b = 0; b < B_Q; ++b) {
                g_v[base + b * D_DIM]   = 0.f;
                g_c[base + b * D_DIM]   = 0.f;
                g_agg[base + b * D_DIM] = 0.f;
            }
            if (lane < T_STEPS)
                *reinterpret_cast<uint4*>(g_smask + (size_t)lane * (N_NODES * B_Q) + n * B_Q) =
                    make_uint4(0u, 0u, 0u, 0u);
            if (lane == 0) g_hot_flag[n] = 0;
        }
    }
}

// ---------------- launch ----------------
extern "C" void kernel_launch(void* const* d_in, const int* in_sizes, int n_in,
                              void* d_out, int out_size) {
    fused_kernel<<<1, 32>>>(
        (const int*)d_in[0], (const int*)d_in[1], (const int*)d_in[2],
        (const int*)d_in[3], (const int*)d_in[4], (const int*)d_in[5],
        (const float*)d_in[6], (const float*)d_in[7], (const float*)d_in[8],
        (const float*)d_in[9], (const float*)d_in[10],
        (const float*)d_in[11], (const float*)d_in[12],
        (const float*)d_in[13], (const float*)d_in[14],
        (float*)d_out);
}

// round 14
// speedup vs baseline: 1.0363x; 1.0207x over previous
#include <cuda_runtime.h>

// ---------------- static problem sizes ----------------
#define N_NODES 20000
#define E_EDGES 320000
#define B_Q 4
#define K_T 32
#define D_DIM 32
#define DR_REL 40
#define T_STEPS 10
#define VTH 2.0f
#define DECAY 0.7788007830714049f   // exp(-1/4)
#define RATIO 0.95f
#define NSCALE 8.025261215232422f   // (1 - 0.95^10) / (1 - 0.95)

// ---------------- persistent state (zero-init; cleanup restores zeros) ----------------
// Fast path touches NONE of these.
__device__ unsigned g_smask[T_STEPS * N_NODES * B_Q];
__device__ float    g_v[N_NODES * B_Q * D_DIM];
__device__ float    g_c[N_NODES * B_Q * D_DIM];
__device__ float    g_agg[N_NODES * B_Q * D_DIM];
__device__ int      g_hot_flag[N_NODES];
__device__ int      g_hot_list[N_NODES];
__device__ float    g_wrel[B_Q * DR_REL * D_DIM];

__global__ __launch_bounds__(32, 1)
void fused_kernel(const int* __restrict__ edge_src,
                  const int* __restrict__ edge_dst,
                  const int* __restrict__ edge_type,
                  const int* __restrict__ h_index,
                  const int* __restrict__ t_index,
                  const int* __restrict__ r_index,
                  const float* __restrict__ query_emb,
                  const float* __restrict__ relw_W,
                  const float* __restrict__ relw_b,
                  const float* __restrict__ lin_W,
                  const float* __restrict__ lin_b,
                  const float* __restrict__ W1,
                  const float* __restrict__ b1,
                  const float* __restrict__ W2,
                  const float* __restrict__ b2,
                  float* __restrict__ out) {
    // slow-path shared (untouched on fast path)
    __shared__ float s_W1[64 * 65];
    __shared__ float s_WT[D_DIM * D_DIM];
    __shared__ float s_q[B_Q * D_DIM];
    __shared__ float s_b1[64], s_W2[64];
    __shared__ int   s_hot, s_fprev, s_fcur, s_wrel_done;

    const int lane = threadIdx.x;            // single warp

    // ---------- ONE parallel load round: no dependent global chains at all ----------
    int r = 0;
    if (lane < B_Q) r = __ldg(r_index + lane);
    // whole query_emb table into registers: lane holds float4 idx s*32+lane, s=0..9
    const float4* qe4p = reinterpret_cast<const float4*>(query_emb);
    float4 qe[10];
#pragma unroll
    for (int s = 0; s < 10; ++s) qe[s] = __ldg(qe4p + s * 32 + lane);
    const float4* W14 = reinterpret_cast<const float4*>(W1);
    float4 wa[8], wb[8];                     // W1[lane][32:64], W1[lane+32][32:64]
#pragma unroll
    for (int qd = 0; qd < 8; ++qd) {
        wa[qd] = __ldg(W14 + lane * 16 + 8 + qd);
        wb[qd] = __ldg(W14 + (lane + 32) * 16 + 8 + qd);
    }
    float b1a = __ldg(b1 + lane), b1b = __ldg(b1 + lane + 32);
    float w2a = __ldg(W2 + lane), w2b = __ldg(W2 + lane + 32);
    float bb2 = __ldg(b2);

    // ---------- register-only gather: q_b[lane] = query_emb[r_b*32 + lane] ----------
    const int c = lane & 3;
    float qb[B_Q];
#pragma unroll
    for (int b = 0; b < B_Q; ++b) {
        int rb = __shfl_sync(0xffffffffu, r, b);         // warp-uniform
        int slot = rb >> 2;                              // uniform 0..9
        float4 v;
        switch (slot) {                                  // uniform branch
            case 0: v = qe[0]; break;  case 1: v = qe[1]; break;
            case 2: v = qe[2]; break;  case 3: v = qe[3]; break;
            case 4: v = qe[4]; break;  case 5: v = qe[5]; break;
            case 6: v = qe[6]; break;  case 7: v = qe[7]; break;
            case 8: v = qe[8]; break;  default: v = qe[9]; break;
        }
        int owner = (rb * 8 + (lane >> 2)) & 31;
        float vx = __shfl_sync(0xffffffffu, v.x, owner);
        float vy = __shfl_sync(0xffffffffu, v.y, owner);
        float vz = __shfl_sync(0xffffffffu, v.z, owner);
        float vw = __shfl_sync(0xffffffffu, v.w, owner);
        qb[b] = (c == 0) ? vx : (c == 1) ? vy : (c == 2) ? vz : vw;
    }
    const float q0 = qb[0], q1 = qb[1], q2 = qb[2], q3 = qb[3];

    // ---------- t=0 ballots (strict decay => spikes only possible at t=0) ----------
    float bd0 = q0 * (VTH * 0.5f) + VTH * 0.5f;
    float bd1 = q1 * (VTH * 0.5f) + VTH * 0.5f;
    float bd2 = q2 * (VTH * 0.5f) + VTH * 0.5f;
    float bd3 = q3 * (VTH * 0.5f) + VTH * 0.5f;
    unsigned m0 = __ballot_sync(0xffffffffu, (bd0 - VTH) >= 0.f);
    unsigned m1 = __ballot_sync(0xffffffffu, (bd1 - VTH) >= 0.f);
    unsigned m2 = __ballot_sync(0xffffffffu, (bd2 - VTH) >= 0.f);
    unsigned m3 = __ballot_sync(0xffffffffu, (bd3 - VTH) >= 0.f);
    const unsigned any = m0 | m1 | m2 | m3;

    // ======================= FAST PATH: no spikes ever =======================
    if (any == 0u) {
        const float* waf = reinterpret_cast<const float*>(wa);
        const float* wbf = reinterpret_cast<const float*>(wb);
        float a00 = b1a, a01 = b1b;
        float a10 = b1a, a11 = b1b;
        float a20 = b1a, a21 = b1b;
        float a30 = b1a, a31 = b1b;
#pragma unroll
        for (int i = 0; i < 32; ++i) {
            float wA = waf[i], wB = wbf[i];
            float c0 = __shfl_sync(0xffffffffu, q0, i);
            float c1 = __shfl_sync(0xffffffffu, q1, i);
            float c2 = __shfl_sync(0xffffffffu, q2, i);
            float c3 = __shfl_sync(0xffffffffu, q3, i);
            a00 = fmaf(c0, wA, a00); a01 = fmaf(c0, wB, a01);
            a10 = fmaf(c1, wA, a10); a11 = fmaf(c1, wB, a11);
            a20 = fmaf(c2, wA, a20); a21 = fmaf(c2, wB, a21);
            a30 = fmaf(c3, wA, a30); a31 = fmaf(c3, wB, a31);
        }
        float h0 = fmaxf(a00, 0.f) * w2a + fmaxf(a01, 0.f) * w2b;
        float h1 = fmaxf(a10, 0.f) * w2a + fmaxf(a11, 0.f) * w2b;
        float h2 = fmaxf(a20, 0.f) * w2a + fmaxf(a21, 0.f) * w2b;
        float h3 = fmaxf(a30, 0.f) * w2a + fmaxf(a31, 0.f) * w2b;
#pragma unroll
        for (int off = 16; off; off >>= 1) {
            h0 += __shfl_down_sync(0xffffffffu, h0, off);
            h1 += __shfl_down_sync(0xffffffffu, h1, off);
            h2 += __shfl_down_sync(0xffffffffu, h2, off);
            h3 += __shfl_down_sync(0xffffffffu, h3, off);
        }
        h0 = __shfl_sync(0xffffffffu, h0, 0) + bb2;
        h1 = __shfl_sync(0xffffffffu, h1, 0) + bb2;
        h2 = __shfl_sync(0xffffffffu, h2, 0) + bb2;
        h3 = __shfl_sync(0xffffffffu, h3, 0) + bb2;
        float sc = (lane < 16) ? ((lane < 8) ? h0 : h1) : ((lane < 24) ? h2 : h3);
        reinterpret_cast<float4*>(out)[lane] = make_float4(sc, sc, sc, sc);
        return;
    }

    // ======================= SLOW PATH (spikes at t=0 exist; single-warp generic) =======================
    s_q[0 * D_DIM + lane] = q0;
    s_q[1 * D_DIM + lane] = q1;
    s_q[2 * D_DIM + lane] = q2;
    s_q[3 * D_DIM + lane] = q3;
    for (int i = lane; i < 64; i += 32) { s_b1[i] = __ldg(b1 + i); s_W2[i] = __ldg(W2 + i); }
    for (int k = lane; k < 1024; k += 32) {              // full W1 into padded shared
        float4 v = __ldg(W14 + k);
        float* dst = s_W1 + (k >> 4) * 65 + ((k & 15) << 2);
        dst[0] = v.x; dst[1] = v.y; dst[2] = v.z; dst[3] = v.w;
    }
    for (int i = lane; i < D_DIM * D_DIM; i += 32) {
        int ii = i >> 5, j = i & 31;
        s_WT[i] = lin_W[j * D_DIM + ii];
    }
    if (lane == 0) { s_hot = 0; s_fprev = 0; s_fcur = 0; s_wrel_done = 0; }
    __syncthreads();

    // materialize head-node state at ts = 0
    {
        unsigned ms[4] = {m0, m1, m2, m3};
        for (int b = 0; b < B_Q; ++b) {
            int n = __ldg(h_index + b);
            float bd = s_q[b * D_DIM + lane] * (VTH * 0.5f) + VTH * 0.5f;
            bool sp = (bd - VTH) >= 0.f;
            size_t base = (size_t)(n * B_Q + b) * D_DIM + lane;
            g_v[base] = sp ? 0.f : bd;
            g_c[base] = 0.f;
            if (lane == 0) {
                if (ms[b]) {
                    g_smask[(size_t)(n * B_Q) + b] = ms[b];
                    s_fprev += 1;
                }
                if (atomicExch(&g_hot_flag[n], 1) == 0) {
                    int p = s_hot++;
                    g_hot_list[p] = n;
                }
            }
        }
    }
    __syncthreads();

    const float lb = __ldg(lin_b + lane);
    for (int t = 1; t < T_STEPS; ++t) {
        int fc = s_fprev;
        if (fc != 0) {
            if (!s_wrel_done) {
                for (int id = lane; id < B_Q * DR_REL * D_DIM; id += 32) {
                    int b  = id / (DR_REL * D_DIM);
                    int rd = id % (DR_REL * D_DIM);
                    float acc = relw_b[rd];
#pragma unroll
                    for (int i = 0; i < D_DIM; ++i)
                        acc += s_q[b * D_DIM + i] * relw_W[i * (DR_REL * D_DIM) + rd];
                    g_wrel[id] = acc;
                }
                __syncthreads();
                if (lane == 0) s_wrel_done = 1;
            }
            const unsigned* mp = g_smask + (size_t)(t - 1) * (N_NODES * B_Q);
            for (int e = 0; e < E_EDGES; ++e) {
                int src = __ldg(edge_src + e);
                uint4 m = *reinterpret_cast<const uint4*>(mp + src * 4);
                if (m.x | m.y | m.z | m.w) {
                    int dst = __ldg(edge_dst + e);
                    int ty  = __ldg(edge_type + e);
                    if (lane == 0) {
                        if (atomicExch(&g_hot_flag[dst], 1) == 0) {
                            int p = s_hot++;
                            g_hot_list[p] = dst;
                        }
                    }
                    int off = ty * D_DIM + lane;
                    float* ag = g_agg + (size_t)(dst * B_Q) * D_DIM + lane;
                    if ((m.x >> lane) & 1u) ag[0 * D_DIM] += g_wrel[0 * DR_REL * D_DIM + off];
                    if ((m.y >> lane) & 1u) ag[1 * D_DIM] += g_wrel[1 * DR_REL * D_DIM + off];
                    if ((m.z >> lane) & 1u) ag[2 * D_DIM] += g_wrel[2 * DR_REL * D_DIM + off];
                    if ((m.w >> lane) & 1u) ag[3 * D_DIM] += g_wrel[3 * DR_REL * D_DIM + off];
                }
            }
            __syncthreads();
        }
        int nh = s_hot;
        for (int i = 0; i < nh; ++i) {
            int n = g_hot_list[i];
            size_t base = (size_t)(n * B_Q) * D_DIM + lane;
            float a0 = 0.f, a1 = 0.f, a2 = 0.f, a3 = 0.f;
            if (fc != 0) {
                a0 = g_agg[base + 0 * D_DIM]; g_agg[base + 0 * D_DIM] = 0.f;
                a1 = g_agg[base + 1 * D_DIM]; g_agg[base + 1 * D_DIM] = 0.f;
                a2 = g_agg[base + 2 * D_DIM]; g_agg[base + 2 * D_DIM] = 0.f;
                a3 = g_agg[base + 3 * D_DIM]; g_agg[base + 3 * D_DIM] = 0.f;
            }
            float x0 = lb, x1 = lb, x2 = lb, x3 = lb;
#pragma unroll
            for (int k = 0; k < D_DIM; ++k) {
                float w = s_WT[k * D_DIM + lane];
                x0 = fmaf(__shfl_sync(0xffffffffu, a0, k), w, x0);
                x1 = fmaf(__shfl_sync(0xffffffffu, a1, k), w, x1);
                x2 = fmaf(__shfl_sync(0xffffffffu, a2, k), w, x2);
                x3 = fmaf(__shfl_sync(0xffffffffu, a3, k), w, x3);
            }
            unsigned bm[4];
            float xs[4] = {x0, x1, x2, x3};
#pragma unroll
            for (int b = 0; b < B_Q; ++b) {
                float cc = g_c[base + b * D_DIM] * DECAY + xs[b];
                float vv = g_v[base + b * D_DIM] * DECAY + cc;
                bool sp = (vv - VTH) >= 0.f;
                g_c[base + b * D_DIM] = cc;
                g_v[base + b * D_DIM] = sp ? 0.f : vv;
                bm[b] = __ballot_sync(0xffffffffu, sp);
            }
            if (lane == 0) {
                *reinterpret_cast<uint4*>(g_smask + (size_t)t * (N_NODES * B_Q) + n * B_Q) =
                    make_uint4(bm[0], bm[1], bm[2], bm[3]);
                if (bm[0] | bm[1] | bm[2] | bm[3]) s_fcur += 1;
            }
        }
        __syncthreads();
        if (lane == 0) { s_fprev = s_fcur; s_fcur = 0; }
        __syncthreads();
    }

    // full score: 128 pairs, serial over the single warp
    for (int p = 0; p < B_Q * K_T; ++p) {
        int b = p >> 5;
        int tn = __ldg(t_index + p);
        float e = 0.f, w = 1.0f;
#pragma unroll
        for (int t = 0; t < T_STEPS; ++t) {
            unsigned m = g_smask[(size_t)t * (N_NODES * B_Q) + tn * B_Q + b];
            if ((m >> lane) & 1u) e += w;
            w *= RATIO;
        }
        float f0 = e / NSCALE;
        float f1 = s_q[b * D_DIM + lane];
        float acc0s = s_b1[lane], acc1s = s_b1[lane + 32];
#pragma unroll
        for (int i = 0; i < 32; ++i) {
            float a = __shfl_sync(0xffffffffu, f0, i);
            float cc = __shfl_sync(0xffffffffu, f1, i);
            acc0s = fmaf(a,  s_W1[lane * 65 + i],              acc0s);
            acc0s = fmaf(cc, s_W1[lane * 65 + 32 + i],         acc0s);
            acc1s = fmaf(a,  s_W1[(lane + 32) * 65 + i],       acc1s);
            acc1s = fmaf(cc, s_W1[(lane + 32) * 65 + 32 + i],  acc1s);
        }
        float hs = fmaxf(acc0s, 0.f) * s_W2[lane] + fmaxf(acc1s, 0.f) * s_W2[lane + 32];
#pragma unroll
        for (int off = 16; off; off >>= 1)
            hs += __shfl_down_sync(0xffffffffu, hs, off);
        if (lane == 0) out[p] = hs + bb2;
    }
    __syncthreads();

    // cleanup: restore pristine zeros for next replay
    {
        int nh = s_hot;
        for (int i = 0; i < nh; ++i) {
            int n = g_hot_list[i];
            size_t base = (size_t)(n * B_Q) * D_DIM + lane;
#pragma unroll
            for (int b = 0; b < B_Q; ++b) {
                g_v[base + b * D_DIM]   = 0.f;
                g_c[base + b * D_DIM]   = 0.f;
                g_agg[base + b * D_DIM] = 0.f;
            }
            if (lane < T_STEPS)
                *reinterpret_cast<uint4*>(g_smask + (size_t)lane * (N_NODES * B_Q) + n * B_Q) =
                    make_uint4(0u, 0u, 0u, 0u);
            if (lane == 0) g_hot_flag[n] = 0;
        }
    }
}

// ---------------- launch ----------------
extern "C" void kernel_launch(void* const* d_in, const int* in_sizes, int n_in,
                              void* d_out, int out_size) {
    fused_kernel<<<1, 32>>>(
        (const int*)d_in[0], (const int*)d_in[1], (const int*)d_in[2],
        (const int*)d_in[3], (const int*)d_in[4], (const int*)d_in[5],
        (const float*)d_in[6], (const float*)d_in[7], (const float*)d_in[8],
        (const float*)d_in[9], (const float*)d_in[10],
        (const float*)d_in[11], (const float*)d_in[12],
        (const float*)d_in[13], (const float*)d_in[14],
        (float*)d_out);
}